// round 7
// baseline (speedup 1.0000x reference)
#include <cuda_runtime.h>
#include <cuda_bf16.h>
#include <cstdint>

// Problem constants
#define Uu 8192
#define Ii 4096
#define Kk 256
#define NNZ 409600
#define INV_COEFF (1.0f / 5792.6187514801984f)   // 1/sqrt(U*I)

// ===================== device scratch ======================================
static __device__ __align__(16) __nv_bfloat16 g_CfTH[Kk * Ii], g_CfTL[Kk * Ii];
static __device__ __align__(16) __nv_bfloat16 g_GiTH[Kk * Ii], g_GiTL[Kk * Ii];
static __device__ __align__(16) __nv_bfloat16 g_usfH[Ii * Kk], g_usfL[Ii * Kk];
static __device__ __align__(16) __nv_bfloat16 g_StH[Ii * Kk],  g_StL[Ii * Kk];
static __device__ __align__(16) float g_E1[Uu * Kk];
static __device__ __align__(16) float g_E2[Uu * Kk];
static __device__ __align__(16) float g_Gu[Uu * Kk];
static __device__ unsigned g_colmin[Ii];
static __device__ float    g_colsum[Ii];
static __device__ int      g_minkey[Uu];
static __device__ int      g_rowstart[Uu];
static __device__ int      g_rowcnt[Uu];
static __device__ int      g_colcnt[Ii];
static __device__ int      g_coloff[Ii];
static __device__ int      g_colcur[Ii];
static __device__ int      g_colperm[NNZ];
static __device__ float    g_p1[Uu], g_p2[Uu];
static __device__ int      g_c1[Uu], g_c2[Uu];
static __device__ int      g_has[Uu];

__device__ __forceinline__ unsigned fenc(float f) {
    unsigned u = __float_as_uint(f);
    return (u & 0x80000000u) ? ~u : (u | 0x80000000u);
}
__device__ __forceinline__ float fdec(unsigned e) {
    return (e & 0x80000000u) ? __uint_as_float(e ^ 0x80000000u) : __uint_as_float(~e);
}

// ---------------------------------------------------------------- init
__global__ void init_kernel() {
    int i = blockIdx.x * blockDim.x + threadIdx.x;
    if (i < Ii) { g_colmin[i] = 0xFFFFFFFFu; g_colsum[i] = 0.0f; g_colcnt[i] = 0; }
    if (i < Uu) { g_minkey[i] = 0x7FFFFFFF; g_rowcnt[i] = 0; g_rowstart[i] = 0; }
}

// ------------------------------------------------- build row/col metadata
__global__ void build_kernel(const int* __restrict__ pos_rows,
                             const int* __restrict__ pos_cols) {
    int i = blockIdx.x * blockDim.x + threadIdx.x;
    if (i >= NNZ) return;
    int r = pos_rows[i], c = pos_cols[i];
    atomicAdd(&g_rowcnt[r], 1);
    atomicAdd(&g_colcnt[c], 1);
    if (i == 0 || pos_rows[i - 1] != r) g_rowstart[r] = i;
    atomicMin(&g_minkey[r], c * NNZ + i);
}

// --------------------------------- exclusive scan of column counts (1 block)
__global__ void col_scan_kernel() {
    __shared__ int partial[256];
    int t = threadIdx.x;
    int local[16];
    int s = 0;
#pragma unroll
    for (int j = 0; j < 16; j++) { local[j] = s; s += g_colcnt[t * 16 + j]; }
    partial[t] = s;
    __syncthreads();
    if (t == 0) {
        int run = 0;
        for (int i = 0; i < 256; i++) { int v = partial[i]; partial[i] = run; run += v; }
    }
    __syncthreads();
    int base = partial[t];
#pragma unroll
    for (int j = 0; j < 16; j++) {
        int off = base + local[j];
        g_coloff[t * 16 + j] = off;
        g_colcur[t * 16 + j] = off;
    }
}

// ----------------------------------------- scatter indices sorted by column
__global__ void scatter_kernel(const int* __restrict__ pos_cols) {
    int i = blockIdx.x * blockDim.x + threadIdx.x;
    if (i >= NNZ) return;
    int c = pos_cols[i];
    int p = atomicAdd(&g_colcur[c], 1);
    g_colperm[p] = i;
}

// --------------------------- fp32 -> bf16 hi/lo plane split (vectorized)
__global__ void split_kernel(const float4* __restrict__ src,
                             __nv_bfloat162* __restrict__ hi,
                             __nv_bfloat162* __restrict__ lo, int n4) {
    int i = blockIdx.x * blockDim.x + threadIdx.x;
    if (i >= n4) return;
    float4 v = src[i];
    __nv_bfloat16 hx = __float2bfloat16_rn(v.x);
    __nv_bfloat16 hy = __float2bfloat16_rn(v.y);
    __nv_bfloat16 hz = __float2bfloat16_rn(v.z);
    __nv_bfloat16 hw = __float2bfloat16_rn(v.w);
    hi[2 * i]     = __halves2bfloat162(hx, hy);
    hi[2 * i + 1] = __halves2bfloat162(hz, hw);
    lo[2 * i]     = __halves2bfloat162(__float2bfloat16_rn(v.x - __bfloat162float(hx)),
                                       __float2bfloat16_rn(v.y - __bfloat162float(hy)));
    lo[2 * i + 1] = __halves2bfloat162(__float2bfloat16_rn(v.z - __bfloat162float(hz)),
                                       __float2bfloat16_rn(v.w - __bfloat162float(hw)));
}

// -------- CfT[n,c] = item_sv_f[c,n]/lam_pos[n] -> bf16 hi/lo [256,4096]
__global__ void cft_kernel(const float* __restrict__ isf,
                           const float* __restrict__ lamp) {
    __shared__ float t[32][33];
    int c_in = blockIdx.x * 32 + threadIdx.y;
    int k_in = blockIdx.y * 32 + threadIdx.x;
    t[threadIdx.y][threadIdx.x] = isf[c_in * Kk + k_in] / lamp[k_in];
    __syncthreads();
    int c_out = blockIdx.x * 32 + threadIdx.x;
    int k_out = blockIdx.y * 32 + threadIdx.y;
    float x = t[threadIdx.x][threadIdx.y];
    __nv_bfloat16 h = __float2bfloat16_rn(x);
    g_CfTH[k_out * Ii + c_out] = h;
    g_CfTL[k_out * Ii + c_out] = __float2bfloat16_rn(x - __bfloat162float(h));
}

// ------------------------------------- user GNN: G_u (rows are presorted)
__global__ void user_gnn_kernel(const int* __restrict__ pos_cols,
                                const float* __restrict__ pos_vals,
                                const float* __restrict__ item_sv,
                                const float* __restrict__ user_sv) {
    int r = blockIdx.x, k = threadIdx.x;
    int s0 = g_rowstart[r], n = g_rowcnt[r];
    __shared__ int sc[256];
    __shared__ float sv[256];
    float acc = 0.0f;
    for (int base = 0; base < n; base += 256) {
        int j = base + k;
        if (j < n) { sc[k] = pos_cols[s0 + j]; sv[k] = pos_vals[s0 + j]; }
        __syncthreads();
        int lim = min(256, n - base);
        int jj = 0;
        for (; jj + 4 <= lim; jj += 4) {
            int c0 = sc[jj], c1 = sc[jj + 1], c2 = sc[jj + 2], c3 = sc[jj + 3];
            float v0 = sv[jj], v1 = sv[jj + 1], v2 = sv[jj + 2], v3 = sv[jj + 3];
            float a0 = item_sv[c0 * Kk + k];
            float a1 = item_sv[c1 * Kk + k];
            float a2 = item_sv[c2 * Kk + k];
            float a3 = item_sv[c3 * Kk + k];
            acc += v0 * a0 + v1 * a1 + v2 * a2 + v3 * a3;
        }
        for (; jj < lim; jj++)
            acc += sv[jj] * item_sv[sc[jj] * Kk + k];
        __syncthreads();
    }
    g_Gu[r * Kk + k] = 0.5f * (acc * INV_COEFF + user_sv[r * Kk + k]);
}

// ------------- fused item GNN (/lambda folded, transposed) + St, hi/lo out
__global__ void item_s_kernel(const int* __restrict__ pos_rows,
                              const float* __restrict__ pos_vals,
                              const float* __restrict__ user_sv,
                              const float* __restrict__ item_sv,
                              const float* __restrict__ lambda_mat) {
    int c = blockIdx.x, k = threadIdx.x;
    int s0 = g_coloff[c], n = g_colcnt[c];
    __shared__ int sr[256];
    __shared__ float sv[256];
    float accI = 0.0f, accS = 0.0f;
    for (int base = 0; base < n; base += 256) {
        int j = base + k;
        if (j < n) {
            int p = g_colperm[s0 + j];
            sr[k] = pos_rows[p];
            sv[k] = pos_vals[p];
        }
        __syncthreads();
        int lim = min(256, n - base);
        int jj = 0;
        for (; jj + 4 <= lim; jj += 4) {
            int r0 = sr[jj], r1 = sr[jj + 1], r2 = sr[jj + 2], r3 = sr[jj + 3];
            float v0 = sv[jj], v1 = sv[jj + 1], v2 = sv[jj + 2], v3 = sv[jj + 3];
            float u0 = user_sv[r0 * Kk + k];
            float u1 = user_sv[r1 * Kk + k];
            float u2 = user_sv[r2 * Kk + k];
            float u3 = user_sv[r3 * Kk + k];
            float g0 = g_Gu[r0 * Kk + k];
            float g1 = g_Gu[r1 * Kk + k];
            float g2 = g_Gu[r2 * Kk + k];
            float g3 = g_Gu[r3 * Kk + k];
            accI += v0 * u0 + v1 * u1 + v2 * u2 + v3 * u3;
            accS += v0 * g0 + v1 * g1 + v2 * g2 + v3 * g3;
        }
        for (; jj < lim; jj++) {
            int r = sr[jj];
            float v = sv[jj];
            accI += v * user_sv[r * Kk + k];
            accS += v * g_Gu[r * Kk + k];
        }
        __syncthreads();
    }
    float gi = 0.5f * (accI * INV_COEFF + item_sv[c * Kk + k]) / lambda_mat[k];
    __nv_bfloat16 gih = __float2bfloat16_rn(gi);
    g_GiTH[k * Ii + c] = gih;
    g_GiTL[k * Ii + c] = __float2bfloat16_rn(gi - __bfloat162float(gih));
    __nv_bfloat16 sh = __float2bfloat16_rn(accS);
    g_StH[c * Kk + k] = sh;
    g_StL[c * Kk + k] = __float2bfloat16_rn(accS - __bfloat162float(sh));
}

// ===================== mma.sync bf16-split GEMM ============================
// D[M,N] = A[M,K] @ B[N,K]^T via 3-term bf16 split, fp32 accumulation.
// A is fp32 in GMEM; split into hi/lo bf16 fragments on the fly at
// fragment-load time (saves the separate split pass; same DRAM bytes).
// B is pre-split hi/lo bf16 planes.
// BM=BN=128, BK=32, 256 threads (8 warps, 2x4), warp tile 64x32.
// MODE 0: store fp32 C.  MODE 1: per-column min/sum atomics (stats).

__device__ __forceinline__ void cp16(uint32_t dst, const void* src) {
    asm volatile("cp.async.cg.shared.global [%0], [%1], 16;"
                 :: "r"(dst), "l"(__cvta_generic_to_global(src)));
}
#define CP_COMMIT() asm volatile("cp.async.commit_group;")
#define CP_WAIT1()  asm volatile("cp.async.wait_group 1;")

__device__ __forceinline__ uint32_t smem_u32(const void* p) {
    uint32_t a;
    asm("{ .reg .u64 t; cvta.to.shared.u64 t, %1; cvt.u32.u64 %0, t; }"
        : "=r"(a) : "l"(p));
    return a;
}

#define MMA_BF16(d, a, b) \
    asm volatile("mma.sync.aligned.m16n8k16.row.col.f32.bf16.bf16.f32 " \
        "{%0,%1,%2,%3}, {%4,%5,%6,%7}, {%8,%9}, {%0,%1,%2,%3};" \
        : "+f"((d)[0]), "+f"((d)[1]), "+f"((d)[2]), "+f"((d)[3]) \
        : "r"((a)[0]), "r"((a)[1]), "r"((a)[2]), "r"((a)[3]), \
          "r"((b)[0]), "r"((b)[1]))

// fp32 pair -> packed bf16x2 hi + lo (lo = round(x - hi_as_f32))
__device__ __forceinline__ void conv_pair(float2 f, uint32_t& hi, uint32_t& lo) {
    __nv_bfloat162 h2 = __floats2bfloat162_rn(f.x, f.y);   // low = f.x
    uint32_t h = *reinterpret_cast<uint32_t*>(&h2);
    float hx = __uint_as_float(h << 16);
    float hy = __uint_as_float(h & 0xFFFF0000u);
    __nv_bfloat162 l2 = __floats2bfloat162_rn(f.x - hx, f.y - hy);
    hi = h;
    lo = *reinterpret_cast<uint32_t*>(&l2);
}

// stage layout: A fp32 tile 128x32 (16KB, chunk-rotated) | BH 8KB | BL 8KB
#define A_BYTES 16384
#define BH_OFF  16384
#define BL_OFF  24576
#define STAGE   32768

template <int MODE>
__device__ __forceinline__ void gemm_core(
    int M, int N, int K,
    const float* __restrict__ A,
    const __nv_bfloat16* __restrict__ BH, const __nv_bfloat16* __restrict__ BL,
    float* __restrict__ C, unsigned* cmin, float* csum, char* dsm)
{
    __shared__ unsigned sMin[128];
    __shared__ float sSum[128];

    int tid = threadIdx.x;
    int l = tid & 31, wid = tid >> 5;
    int wm = wid >> 2, wn = wid & 3;             // 2 x 4 warps
    int m0 = blockIdx.y * 128, n0 = blockIdx.x * 128;

    if (MODE == 1 && tid < 128) { sMin[tid] = 0xFFFFFFFFu; sSum[tid] = 0.0f; }

    float acc[4][4][4];
#pragma unroll
    for (int a = 0; a < 4; a++)
#pragma unroll
        for (int b = 0; b < 4; b++)
#pragma unroll
            for (int c = 0; c < 4; c++) acc[a][b][c] = 0.0f;

    uint32_t sb = smem_u32(dsm);
    int r_ld = tid >> 1;                   // row 0..127 (A and B planes)
    int asel = (tid & 1) * 4;              // A: 4 of 8 16B-chunks per row
    int bsel = (tid & 1) * 2;              // B: 2 of 4 16B-chunks per row
    int csw = (r_ld >> 1) & 3;             // B chunk swizzle
    int arot = r_ld & 7;                   // A chunk rotation

    int NIT = K >> 5;

    auto load_stage = [&](int s, int it) {
        uint32_t stb = sb + s * STAGE;
        int k0 = it << 5;
        const float* a = A + (size_t)(m0 + r_ld) * K + k0;
        const __nv_bfloat16* bh = BH + (size_t)(n0 + r_ld) * K + k0;
        const __nv_bfloat16* bl = BL + (size_t)(n0 + r_ld) * K + k0;
#pragma unroll
        for (int c = asel; c < asel + 4; c++) {
            int phys = (c + arot) & 7;
            cp16(stb + r_ld * 128 + phys * 16, a + c * 4);
        }
#pragma unroll
        for (int c = bsel; c < bsel + 2; c++) {
            uint32_t off = r_ld * 64 + ((c ^ csw) & 3) * 16;
            cp16(stb + BH_OFF + off, bh + c * 8);
            cp16(stb + BL_OFF + off, bl + c * 8);
        }
    };

    load_stage(0, 0);
    CP_COMMIT();

    for (int it = 0; it < NIT; it++) {
        if (it + 1 < NIT) load_stage((it + 1) & 1, it + 1);
        CP_COMMIT();
        CP_WAIT1();
        __syncthreads();

        const char* st = dsm + (it & 1) * STAGE;
#pragma unroll
        for (int ks = 0; ks < 2; ks++) {
            uint32_t ah[4][4], al4[4][4], bh[4][2], bl4[4][2];
#pragma unroll
            for (int mt = 0; mt < 4; mt++) {
                int row = wm * 64 + mt * 16 + (l >> 2);
                int rot = row & 7;                       // same for row+8
                int chunk0 = ks * 4 + ((l & 3) >> 1);
                int half = (l & 1) * 8;
                uint32_t b0 = row * 128 + (((chunk0)     + rot) & 7) * 16 + half;
                uint32_t b2 = row * 128 + (((chunk0 + 2) + rot) & 7) * 16 + half;
                float2 f00 = *(const float2*)(st + b0);
                float2 f10 = *(const float2*)(st + b0 + 1024);  // row + 8
                float2 f01 = *(const float2*)(st + b2);
                float2 f11 = *(const float2*)(st + b2 + 1024);
                conv_pair(f00, ah[mt][0], al4[mt][0]);
                conv_pair(f10, ah[mt][1], al4[mt][1]);
                conv_pair(f01, ah[mt][2], al4[mt][2]);
                conv_pair(f11, ah[mt][3], al4[mt][3]);
            }
#pragma unroll
            for (int nt = 0; nt < 4; nt++) {
                int row = wn * 32 + nt * 8 + (l >> 2);
                int f = (row & 6) << 1;
                int cp0 = ks * 8 + (l & 3);
                uint32_t o0 = row * 64 + ((cp0 ^ f) << 2);
                uint32_t o1 = row * 64 + (((cp0 + 4) ^ f) << 2);
                bh[nt][0] = *(const uint32_t*)(st + BH_OFF + o0);
                bh[nt][1] = *(const uint32_t*)(st + BH_OFF + o1);
                bl4[nt][0] = *(const uint32_t*)(st + BL_OFF + o0);
                bl4[nt][1] = *(const uint32_t*)(st + BL_OFF + o1);
            }
#pragma unroll
            for (int mt = 0; mt < 4; mt++)
#pragma unroll
                for (int nt = 0; nt < 4; nt++) {
                    MMA_BF16(acc[mt][nt], ah[mt], bh[nt]);
                    MMA_BF16(acc[mt][nt], ah[mt], bl4[nt]);
                    MMA_BF16(acc[mt][nt], al4[mt], bh[nt]);
                }
        }
        __syncthreads();
    }

    // ---------------- epilogue ----------------
    if (MODE == 0) {
#pragma unroll
        for (int mt = 0; mt < 4; mt++) {
            int row = m0 + wm * 64 + mt * 16 + (l >> 2);
#pragma unroll
            for (int nt = 0; nt < 4; nt++) {
                int col = n0 + wn * 32 + nt * 8 + ((l & 3) << 1);
                *(float2*)&C[(size_t)row * N + col] =
                    make_float2(acc[mt][nt][0], acc[mt][nt][1]);
                *(float2*)&C[(size_t)(row + 8) * N + col] =
                    make_float2(acc[mt][nt][2], acc[mt][nt][3]);
            }
        }
    } else {   // MODE 1: fused column min/sum
#pragma unroll
        for (int nt = 0; nt < 4; nt++) {
            float mn0 = acc[0][nt][0], sm0 = 0.0f;
            float mn1 = acc[0][nt][1], sm1 = 0.0f;
#pragma unroll
            for (int mt = 0; mt < 4; mt++) {
                mn0 = fminf(mn0, fminf(acc[mt][nt][0], acc[mt][nt][2]));
                sm0 += acc[mt][nt][0] + acc[mt][nt][2];
                mn1 = fminf(mn1, fminf(acc[mt][nt][1], acc[mt][nt][3]));
                sm1 += acc[mt][nt][1] + acc[mt][nt][3];
            }
#pragma unroll
            for (int d = 4; d < 32; d <<= 1) {
                sm0 += __shfl_xor_sync(0xFFFFFFFFu, sm0, d);
                sm1 += __shfl_xor_sync(0xFFFFFFFFu, sm1, d);
                mn0 = fminf(mn0, __shfl_xor_sync(0xFFFFFFFFu, mn0, d));
                mn1 = fminf(mn1, __shfl_xor_sync(0xFFFFFFFFu, mn1, d));
            }
            if ((l >> 2) == 0) {
                int c = wn * 32 + nt * 8 + ((l & 3) << 1);
                atomicMin(&sMin[c], fenc(mn0));
                atomicAdd(&sSum[c], sm0);
                atomicMin(&sMin[c + 1], fenc(mn1));
                atomicAdd(&sSum[c + 1], sm1);
            }
        }
        __syncthreads();
        if (tid < 128) {
            atomicMin(&cmin[n0 + tid], sMin[tid]);
            atomicAdd(&csum[n0 + tid], sSum[tid]);
        }
    }
}

// wrappers
struct G12P {
    const float* A[2];
    const __nv_bfloat16 *BH[2], *BL[2];
    float* C[2];
};

__global__ void __launch_bounds__(256, 1) gemm12_kernel(G12P p) {
    extern __shared__ char dsm[];
    int z = blockIdx.z;
    gemm_core<0>(Uu, Kk, Ii, p.A[z], p.BH[z], p.BL[z], p.C[z],
                 nullptr, nullptr, dsm);
}

__global__ void __launch_bounds__(256, 1) gemm_stats_kernel(
    const float* A, const __nv_bfloat16* BH, const __nv_bfloat16* BL,
    unsigned* cmin, float* csum) {
    extern __shared__ char dsm[];
    gemm_core<1>(Uu, Ii, Kk, A, BH, BL, nullptr, cmin, csum, dsm);
}

__global__ void __launch_bounds__(256, 1) gemm_out_kernel(
    const float* A, const __nv_bfloat16* BH, const __nv_bfloat16* BL,
    float* C) {
    extern __shared__ char dsm[];
    gemm_core<0>(Uu, Ii, Kk, A, BH, BL, C, nullptr, nullptr, dsm);
}

// ------------------- per-row mat_expo entries -> p1/p2 (compute_P fusion)
__global__ void entry_kernel(const int* __restrict__ pos_cols,
                             const float* __restrict__ pos_vals,
                             const float* __restrict__ usf) {
    int r = blockIdx.x, t = threadIdx.x;
    int mk = g_minkey[r];
    if (mk == 0x7FFFFFFF) { if (t == 0) g_has[r] = 0; return; }
    int eidx = mk % NNZ;
    int c1 = pos_cols[eidx];
    float v1 = pos_vals[eidx];
    int c2 = (c1 + 1) & (Ii - 1);
    float a = g_E1[r * Kk + t];
    float e1 = a * usf[c1 * Kk + t];
    float e2 = a * usf[c2 * Kk + t];
    __shared__ float s1[256], s2[256];
    s1[t] = e1; s2[t] = e2;
    __syncthreads();
    for (int off = 128; off > 0; off >>= 1) {
        if (t < off) { s1[t] += s1[t + off]; s2[t] += s2[t + off]; }
        __syncthreads();
    }
    if (t == 0) {
        float E1v = s1[0], E2v = s2[0];
        float m1 = fdec(g_colmin[c1]), m2 = fdec(g_colmin[c2]);
        float sum1 = g_colsum[c1] - (float)Uu * m1 + (float)Uu * 1e-8f;
        float sum2 = g_colsum[c2] - (float)Uu * m2 + (float)Uu * 1e-8f;
        float n1 = (E1v - m1 + 1e-8f) / sum1;
        float n2 = (E2v - m2 + 1e-8f) / sum2;
        float d1 = (v1 == 0.0f) ? 1e-5f : v1;
        float d2 = (v1 == 0.0f) ? 1e-5f : -v1;
        g_p1[r] = n1 / d1;
        g_p2[r] = n2 / d2;
        g_c1[r] = c1;
        g_c2[r] = c2;
        g_has[r] = 1;
    }
}

// ------------------------------------------- out += 0.2 * mat_adjust
__global__ void adjust_kernel(float* __restrict__ out) {
    int r = blockIdx.x * blockDim.x + threadIdx.x;
    if (r >= Uu || !g_has[r]) return;
    out[(size_t)r * Ii + g_c1[r]] += 0.2f * g_p1[r];
    out[(size_t)r * Ii + g_c2[r]] += 0.2f * g_p2[r];
}

extern "C" void kernel_launch(void* const* d_in, const int* in_sizes, int n_in,
                              void* d_out, int out_size) {
    const float* adj       = (const float*)d_in[0];
    const float* norm_adj  = (const float*)d_in[1];
    const float* user_sv   = (const float*)d_in[2];
    const float* item_sv   = (const float*)d_in[3];
    const float* user_sv_f = (const float*)d_in[4];
    const float* item_sv_f = (const float*)d_in[5];
    const int*   pos_rows  = (const int*)d_in[6];
    const int*   pos_cols  = (const int*)d_in[7];
    const float* pos_vals  = (const float*)d_in[8];
    const float* lambda_m  = (const float*)d_in[9];
    const float* lambda_p  = (const float*)d_in[10];
    float* out = (float*)d_out;

    void *cfH, *cfL, *giH, *giL, *usH, *usL, *stH, *stL, *e1f, *e2f;
    void *cminp, *csump;
    cudaGetSymbolAddress(&cfH, g_CfTH);  cudaGetSymbolAddress(&cfL, g_CfTL);
    cudaGetSymbolAddress(&giH, g_GiTH);  cudaGetSymbolAddress(&giL, g_GiTL);
    cudaGetSymbolAddress(&usH, g_usfH);  cudaGetSymbolAddress(&usL, g_usfL);
    cudaGetSymbolAddress(&stH, g_StH);   cudaGetSymbolAddress(&stL, g_StL);
    cudaGetSymbolAddress(&e1f, g_E1);    cudaGetSymbolAddress(&e2f, g_E2);
    cudaGetSymbolAddress(&cminp, g_colmin); cudaGetSymbolAddress(&csump, g_colsum);

    cudaFuncSetAttribute(gemm12_kernel, cudaFuncAttributeMaxDynamicSharedMemorySize, 65536);
    cudaFuncSetAttribute(gemm_stats_kernel, cudaFuncAttributeMaxDynamicSharedMemorySize, 65536);
    cudaFuncSetAttribute(gemm_out_kernel, cudaFuncAttributeMaxDynamicSharedMemorySize, 65536);

    // 1. metadata init
    init_kernel<<<Uu / 256, 256>>>();
    // 2. row/col counts, row starts, per-row min key
    build_kernel<<<(NNZ + 255) / 256, 256>>>(pos_rows, pos_cols);
    // 3. column offsets (counting sort)
    col_scan_kernel<<<1, 256>>>();
    // 4. column-sorted permutation
    scatter_kernel<<<(NNZ + 255) / 256, 256>>>(pos_cols);
    // 5. small-operand prep: usf planes + CfT planes
    split_kernel<<<(Ii * Kk / 4 + 255) / 256, 256>>>(
        (const float4*)user_sv_f, (__nv_bfloat162*)usH, (__nv_bfloat162*)usL, Ii * Kk / 4);
    cft_kernel<<<dim3(Ii / 32, Kk / 32), dim3(32, 32)>>>(item_sv_f, lambda_p);
    // 6. user GNN smoothing
    user_gnn_kernel<<<Uu, 256>>>(pos_cols, pos_vals, item_sv, user_sv);
    // 7. fused item GNN (-> GiT hi/lo) + St = (G_u^T @ pos_dense)^T hi/lo
    item_s_kernel<<<Ii, 256>>>(pos_rows, pos_vals, user_sv, item_sv, lambda_m);
    // 8+9. E1 = adj @ CfT^T, E2 = norm_adj @ GiT^T (fused fp32-A split, grid.z=2)
    {
        G12P p;
        p.A[0] = adj;      p.BH[0] = (const __nv_bfloat16*)cfH;
        p.BL[0] = (const __nv_bfloat16*)cfL; p.C[0] = (float*)e1f;
        p.A[1] = norm_adj; p.BH[1] = (const __nv_bfloat16*)giH;
        p.BL[1] = (const __nv_bfloat16*)giL; p.C[1] = (float*)e2f;
        gemm12_kernel<<<dim3(Kk / 128, Uu / 128, 2), 256, 65536>>>(p);
    }
    // 10. mat_expo column stats: E1 @ user_sv_f[:Ii]^T, fused min/sum
    gemm_stats_kernel<<<dim3(Ii / 128, Uu / 128), 256, 65536>>>(
        (const float*)e1f, (const __nv_bfloat16*)usH, (const __nv_bfloat16*)usL,
        (unsigned*)cminp, (float*)csump);
    // 11. per-row mat_expo entries -> p1/p2
    entry_kernel<<<Uu, 256>>>(pos_cols, pos_vals, user_sv_f);
    // 12. out = E2 @ St^T
    gemm_out_kernel<<<dim3(Ii / 128, Uu / 128), 256, 65536>>>(
        (const float*)e2f, (const __nv_bfloat16*)stH, (const __nv_bfloat16*)stL, out);
    // 13. out += 0.2 * mat_adjust
    adjust_kernel<<<Uu / 256, 256>>>(out);
}